// round 3
// baseline (speedup 1.0000x reference)
#include <cuda_runtime.h>
#include <cuda_bf16.h>
#include <math.h>

// ---------------------------------------------------------------------------
// MoE router (TOP_K=2, N_EXP=8). Output layout (float32, flattened tuple):
//   [0..8)                      used_capacity
//   [8 .. 8+N*8*C)              cb_weight[N,8,C]
//   [8+N*8*C .. 8+2*N*8*C)      sec_mask[N,8,C] (0.0/1.0)
// ---------------------------------------------------------------------------

#define N_EXP 8
#define MAXN 65536

__device__ int   g_eidx[2 * MAXN];   // [k*N + n] -> expert of k-th choice
__device__ float g_pval[2 * MAXN];   // [k*N + n] -> softmax prob of that expert

// ---------------------------------------------------------------------------
// Kernel A: logits = x @ w_g^T, top-2 (lowest-index tie break), softmax.
// 4 tokens per warp: each shared w_g load is reused across 4 tokens, cutting
// LDS traffic 4x vs the 1-token/warp version. Lanes 0-3 finalize one token.
// ---------------------------------------------------------------------------
__global__ void __launch_bounds__(256) router_topk_kernel(
    const float* __restrict__ x, const float* __restrict__ w_g, int N)
{
    __shared__ float4 ws[N_EXP * 256];  // 8 x 1024 floats (D=1024)

    const int tid  = threadIdx.x;
    const int warp = tid >> 5;
    const int lane = tid & 31;

    const float4* wg4 = reinterpret_cast<const float4*>(w_g);
#pragma unroll
    for (int r = 0; r < 8; r++)
        ws[r * 256 + tid] = wg4[r * 256 + tid];
    __syncthreads();

    const int tok0 = blockIdx.x * 32 + warp * 4;  // 8 warps x 4 tokens
    const float4* x4 = reinterpret_cast<const float4*>(x) + (size_t)tok0 * 256;

    float acc[4][N_EXP];
#pragma unroll
    for (int t = 0; t < 4; t++)
#pragma unroll
        for (int e = 0; e < N_EXP; e++) acc[t][e] = 0.0f;

    const bool full = (tok0 + 3) < N;

#pragma unroll
    for (int j = 0; j < 8; j++) {
        float4 xv[4];
#pragma unroll
        for (int t = 0; t < 4; t++) {
            if (full || (tok0 + t) < N)
                xv[t] = x4[t * 256 + j * 32 + lane];
            else
                xv[t] = make_float4(0.f, 0.f, 0.f, 0.f);
        }
#pragma unroll
        for (int e = 0; e < N_EXP; e++) {
            float4 wv = ws[e * 256 + j * 32 + lane];
#pragma unroll
            for (int t = 0; t < 4; t++)
                acc[t][e] += xv[t].x * wv.x + xv[t].y * wv.y +
                             xv[t].z * wv.z + xv[t].w * wv.w;
        }
    }

    // butterfly reduce: every lane ends with all 32 sums
#pragma unroll
    for (int off = 16; off > 0; off >>= 1)
#pragma unroll
        for (int t = 0; t < 4; t++)
#pragma unroll
            for (int e = 0; e < N_EXP; e++)
                acc[t][e] += __shfl_xor_sync(0xFFFFFFFFu, acc[t][e], off);

    if (lane < 4) {
        const int t = lane;
        const int token = tok0 + t;
        if (token < N) {
            float a[N_EXP];
#pragma unroll
            for (int e = 0; e < N_EXP; e++) a[e] = acc[t][e];

            int e0 = 0; float b0 = a[0];
#pragma unroll
            for (int e = 1; e < N_EXP; e++)
                if (a[e] > b0) { b0 = a[e]; e0 = e; }
            int e1 = (e0 == 0) ? 1 : 0; float b1 = a[e1];
#pragma unroll
            for (int e = 0; e < N_EXP; e++)
                if (e != e0 && a[e] > b1) { b1 = a[e]; e1 = e; }

            float sum = 0.0f;
#pragma unroll
            for (int e = 0; e < N_EXP; e++) sum += expf(a[e] - b0);
            float inv = 1.0f / sum;

            g_eidx[token]     = e0;
            g_eidx[N + token] = e1;
            g_pval[token]     = inv;              // expf(0)*inv
            g_pval[N + token] = expf(b1 - b0) * inv;
        }
    }
}

// ---------------------------------------------------------------------------
// Kernel B: ordered per-expert rank (cumsum in k-major, token order) via
// match_any + popc within warp, per-expert cross-warp scan by warps 0..7,
// direct scatter of cb_weight / sec_mask nonzeros + used_capacity.
// Single block, deterministic. Runs after the memset in stream order.
// ---------------------------------------------------------------------------
__global__ void __launch_bounds__(1024) rank_scatter_kernel(
    float* __restrict__ out, int N, int C)
{
    const int tid  = threadIdx.x;
    const int warp = tid >> 5;
    const int lane = tid & 31;
    const int total = 2 * N;

    __shared__ int warpcnt[N_EXP][32];
    __shared__ int basesh[N_EXP][32];
    __shared__ int running[N_EXP];
    if (tid < N_EXP) running[tid] = 0;

    const size_t rowsC = (size_t)N * N_EXP * (size_t)C;

    const int rounds = (total + 1023) >> 10;
    for (int rd = 0; rd < rounds; rd++) {
        const int i = rd * 1024 + tid;
        const int e = (i < total) ? g_eidx[i] : -1;

        if (tid < N_EXP * 32) ((int*)warpcnt)[tid] = 0;
        __syncthreads();

        unsigned m = __match_any_sync(0xFFFFFFFFu, e);
        int lrank  = __popc(m & ((1u << lane) - 1u));
        int leader = __ffs(m) - 1;
        if (e >= 0 && lane == leader)
            warpcnt[e][warp] = __popc(m);
        __syncthreads();

        if (warp < N_EXP) {
            int runv = running[warp];
            int v = warpcnt[warp][lane];
            int s = v;
#pragma unroll
            for (int off = 1; off < 32; off <<= 1) {
                int u = __shfl_up_sync(0xFFFFFFFFu, s, off);
                if (lane >= off) s += u;
            }
            basesh[warp][lane] = runv + s - v;   // exclusive + running
            if (lane == 31) running[warp] = runv + s;
        }
        __syncthreads();

        if (e >= 0) {
            int r = basesh[e][warp] + lrank;
            if (r < C) {
                int k = (i >= N) ? 1 : 0;
                int n = i - k * N;
                size_t pos = ((size_t)n * N_EXP + e) * (size_t)C + r;
                out[8 + pos]         = g_pval[i];
                out[8 + rowsC + pos] = 1.0f;
            }
        }
        __syncthreads();
    }

    if (tid < N_EXP) {
        int uc = running[tid];
        if (uc > C) uc = C;
        out[tid] = (float)uc;
    }
}

// ---------------------------------------------------------------------------
extern "C" void kernel_launch(void* const* d_in, const int* in_sizes, int n_in,
                              void* d_out, int out_size)
{
    const float* x   = (const float*)d_in[0];
    const float* w_g = (const float*)d_in[1];
    float* out = (float*)d_out;

    const int D = in_sizes[1] / N_EXP;   // 1024
    const int N = in_sizes[0] / D;       // 4096 tokens

    int C = (int)floorf(2.0f * 1.25f * (float)N / (float)N_EXP);
    C += (C & 1);
    if (C < 4) C = 4;

    // 1) zero the full output (bandwidth floor ~45us for 336MB)
    cudaMemsetAsync(d_out, 0, (size_t)out_size * sizeof(float));

    // 2) router: logits + top-2 + softmax probs (4 tokens/warp)
    int blocks = (N + 31) / 32;
    router_topk_kernel<<<blocks, 256>>>(x, w_g, N);

    // 3) ordered ranks + capacity drop + direct scatter + used_capacity
    rank_scatter_kernel<<<1, 1024>>>(out, N, C);
}

// round 4
// speedup vs baseline: 1.1112x; 1.1112x over previous
#include <cuda_runtime.h>
#include <cuda_bf16.h>
#include <math.h>

// ---------------------------------------------------------------------------
// MoE router (TOP_K=2, N_EXP=8). Output layout (float32, flattened tuple):
//   [0..8)                      used_capacity
//   [8 .. 8+N*8*C)              cb_weight[N,8,C]
//   [8+N*8*C .. 8+2*N*8*C)      sec_mask[N,8,C] (0.0/1.0)
// ---------------------------------------------------------------------------

#define N_EXP 8
#define MAXN 65536

__device__ int   g_eidx[2 * MAXN];   // [k*N + n] -> expert of k-th choice
__device__ float g_pval[2 * MAXN];   // [k*N + n] -> softmax prob of that expert
__device__ int   g_rank[2 * MAXN];   // [k*N + n] -> rank within expert queue
__device__ int   g_total[N_EXP];     // per-expert routed counts (pre-clamp)

// ---------------------------------------------------------------------------
// Kernel A: logits = x @ w_g^T, top-2 (lowest-index tie break), softmax.
// 4 tokens per warp; w_g staged in shared, each LDS reused across 4 tokens.
// ---------------------------------------------------------------------------
__global__ void __launch_bounds__(256) router_topk_kernel(
    const float* __restrict__ x, const float* __restrict__ w_g, int N)
{
    __shared__ float4 ws[N_EXP * 256];  // 8 x 1024 floats (D=1024)

    const int tid  = threadIdx.x;
    const int warp = tid >> 5;
    const int lane = tid & 31;

    const float4* wg4 = reinterpret_cast<const float4*>(w_g);
#pragma unroll
    for (int r = 0; r < 8; r++)
        ws[r * 256 + tid] = wg4[r * 256 + tid];
    __syncthreads();

    const int tok0 = blockIdx.x * 32 + warp * 4;  // 8 warps x 4 tokens
    const float4* x4 = reinterpret_cast<const float4*>(x) + (size_t)tok0 * 256;

    float acc[4][N_EXP];
#pragma unroll
    for (int t = 0; t < 4; t++)
#pragma unroll
        for (int e = 0; e < N_EXP; e++) acc[t][e] = 0.0f;

    const bool full = (tok0 + 3) < N;

#pragma unroll
    for (int j = 0; j < 8; j++) {
        float4 xv[4];
#pragma unroll
        for (int t = 0; t < 4; t++) {
            if (full || (tok0 + t) < N)
                xv[t] = x4[t * 256 + j * 32 + lane];
            else
                xv[t] = make_float4(0.f, 0.f, 0.f, 0.f);
        }
#pragma unroll
        for (int e = 0; e < N_EXP; e++) {
            float4 wv = ws[e * 256 + j * 32 + lane];
#pragma unroll
            for (int t = 0; t < 4; t++)
                acc[t][e] += xv[t].x * wv.x + xv[t].y * wv.y +
                             xv[t].z * wv.z + xv[t].w * wv.w;
        }
    }

#pragma unroll
    for (int off = 16; off > 0; off >>= 1)
#pragma unroll
        for (int t = 0; t < 4; t++)
#pragma unroll
            for (int e = 0; e < N_EXP; e++)
                acc[t][e] += __shfl_xor_sync(0xFFFFFFFFu, acc[t][e], off);

    if (lane < 4) {
        const int t = lane;
        const int token = tok0 + t;
        if (token < N) {
            float a[N_EXP];
#pragma unroll
            for (int e = 0; e < N_EXP; e++) a[e] = acc[t][e];

            int e0 = 0; float b0 = a[0];
#pragma unroll
            for (int e = 1; e < N_EXP; e++)
                if (a[e] > b0) { b0 = a[e]; e0 = e; }
            int e1 = (e0 == 0) ? 1 : 0; float b1 = a[e1];
#pragma unroll
            for (int e = 0; e < N_EXP; e++)
                if (e != e0 && a[e] > b1) { b1 = a[e]; e1 = e; }

            float sum = 0.0f;
#pragma unroll
            for (int e = 0; e < N_EXP; e++) sum += expf(a[e] - b0);
            float inv = 1.0f / sum;

            g_eidx[token]     = e0;
            g_eidx[N + token] = e1;
            g_pval[token]     = inv;              // expf(0)*inv
            g_pval[N + token] = expf(b1 - b0) * inv;
        }
    }
}

// ---------------------------------------------------------------------------
// Kernel B: ordered per-expert rank (cumsum in k-major, token order) via
// match_any + popc within warp, per-expert cross-warp scan by warps 0..7.
// PURE COMPUTE: writes only compact g_rank / g_total device globals.
// ---------------------------------------------------------------------------
__global__ void __launch_bounds__(1024) rank_kernel(int N)
{
    const int tid  = threadIdx.x;
    const int warp = tid >> 5;
    const int lane = tid & 31;
    const int total = 2 * N;

    __shared__ int warpcnt[N_EXP][32];
    __shared__ int basesh[N_EXP][32];
    __shared__ int running[N_EXP];
    if (tid < N_EXP) running[tid] = 0;

    const int rounds = (total + 1023) >> 10;
    for (int rd = 0; rd < rounds; rd++) {
        const int i = rd * 1024 + tid;
        const int e = (i < total) ? g_eidx[i] : -1;

        if (tid < N_EXP * 32) ((int*)warpcnt)[tid] = 0;
        __syncthreads();

        unsigned m = __match_any_sync(0xFFFFFFFFu, e);
        int lrank  = __popc(m & ((1u << lane) - 1u));
        int leader = __ffs(m) - 1;
        if (e >= 0 && lane == leader)
            warpcnt[e][warp] = __popc(m);
        __syncthreads();

        if (warp < N_EXP) {
            int runv = running[warp];
            int v = warpcnt[warp][lane];
            int s = v;
#pragma unroll
            for (int off = 1; off < 32; off <<= 1) {
                int u = __shfl_up_sync(0xFFFFFFFFu, s, off);
                if (lane >= off) s += u;
            }
            basesh[warp][lane] = runv + s - v;   // exclusive + running
            if (lane == 31) running[warp] = runv + s;
        }
        __syncthreads();

        if (e >= 0)
            g_rank[i] = basesh[e][warp] + lrank;
        __syncthreads();
    }

    if (tid < N_EXP)
        g_total[tid] = running[tid];
}

// ---------------------------------------------------------------------------
// Kernel C: wide-grid scatter. One thread per routed entry: at most 2 stores
// into the (already-zeroed) output. Block 0 also writes used_capacity.
// ---------------------------------------------------------------------------
__global__ void __launch_bounds__(256) scatter_kernel(
    float* __restrict__ out, int N, int C)
{
    const int i = blockIdx.x * blockDim.x + threadIdx.x;
    const int total = 2 * N;
    const size_t rowsC = (size_t)N * N_EXP * (size_t)C;

    if (i < total) {
        int r = g_rank[i];
        if (r < C) {
            int e = g_eidx[i];
            int k = (i >= N) ? 1 : 0;
            int n = i - k * N;
            size_t pos = ((size_t)n * N_EXP + e) * (size_t)C + r;
            out[8 + pos]         = g_pval[i];
            out[8 + rowsC + pos] = 1.0f;
        }
    }

    if (blockIdx.x == 0 && threadIdx.x < N_EXP) {
        int uc = g_total[threadIdx.x];
        if (uc > C) uc = C;
        out[threadIdx.x] = (float)uc;
    }
}

// ---------------------------------------------------------------------------
extern "C" void kernel_launch(void* const* d_in, const int* in_sizes, int n_in,
                              void* d_out, int out_size)
{
    const float* x   = (const float*)d_in[0];
    const float* w_g = (const float*)d_in[1];
    float* out = (float*)d_out;

    const int D = in_sizes[1] / N_EXP;   // 1024
    const int N = in_sizes[0] / D;       // 4096 tokens

    int C = (int)floorf(2.0f * 1.25f * (float)N / (float)N_EXP);
    C += (C & 1);
    if (C < 4) C = 4;

    // 1) zero the full output (bandwidth floor ~45us for 336MB)
    cudaMemsetAsync(d_out, 0, (size_t)out_size * sizeof(float));

    // 2) router: logits + top-2 + softmax probs (4 tokens/warp)
    int blocks = (N + 31) / 32;
    router_topk_kernel<<<blocks, 256>>>(x, w_g, N);

    // 3) ordered ranks (pure compute, single block)
    rank_kernel<<<1, 1024>>>(N);

    // 4) wide-grid scatter + used_capacity
    int sblocks = (2 * N + 255) / 256;
    scatter_kernel<<<sblocks, 256>>>(out, N, C);
}

// round 5
// speedup vs baseline: 1.1523x; 1.0370x over previous
#include <cuda_runtime.h>
#include <cuda_bf16.h>
#include <math.h>

// ---------------------------------------------------------------------------
// MoE router (TOP_K=2, N_EXP=8). Output layout (float32, flattened tuple):
//   [0..8)                      used_capacity
//   [8 .. 8+N*8*C)              cb_weight[N,8,C]
//   [8+N*8*C .. 8+2*N*8*C)      sec_mask[N,8,C] (0.0/1.0)
// ---------------------------------------------------------------------------

#define N_EXP 8
#define MAXN 65536

__device__ int   g_eidx[2 * MAXN];   // [k*N + n] -> expert of k-th choice
__device__ float g_pval[2 * MAXN];   // [k*N + n] -> softmax prob of that expert
__device__ int   g_rank[2 * MAXN];   // [k*N + n] -> rank within expert queue
__device__ int   g_total[N_EXP];     // per-expert routed counts (pre-clamp)

// ---------------------------------------------------------------------------
// Kernel A: logits = x @ w_g^T, top-2 (lowest-index tie break), softmax.
// 2 tokens per warp (LDS amortized 2x vs 1/warp), 256 threads, 16 tokens per
// block -> 256 blocks for N=4096: enough CTAs to cover all 148 SMs.
// ---------------------------------------------------------------------------
__global__ void __launch_bounds__(256) router_topk_kernel(
    const float* __restrict__ x, const float* __restrict__ w_g, int N)
{
    __shared__ float4 ws[N_EXP * 256];  // 8 x 1024 floats (D=1024)

    const int tid  = threadIdx.x;
    const int warp = tid >> 5;
    const int lane = tid & 31;

    const float4* wg4 = reinterpret_cast<const float4*>(w_g);
#pragma unroll
    for (int r = 0; r < 8; r++)
        ws[r * 256 + tid] = wg4[r * 256 + tid];
    __syncthreads();

    const int tok0 = blockIdx.x * 16 + warp * 2;  // 8 warps x 2 tokens
    const float4* x4 = reinterpret_cast<const float4*>(x) + (size_t)tok0 * 256;

    float acc[2][N_EXP];
#pragma unroll
    for (int t = 0; t < 2; t++)
#pragma unroll
        for (int e = 0; e < N_EXP; e++) acc[t][e] = 0.0f;

    const bool full = (tok0 + 1) < N;

#pragma unroll
    for (int j = 0; j < 8; j++) {
        float4 xv[2];
#pragma unroll
        for (int t = 0; t < 2; t++) {
            if (full || (tok0 + t) < N)
                xv[t] = x4[t * 256 + j * 32 + lane];
            else
                xv[t] = make_float4(0.f, 0.f, 0.f, 0.f);
        }
#pragma unroll
        for (int e = 0; e < N_EXP; e++) {
            float4 wv = ws[e * 256 + j * 32 + lane];
#pragma unroll
            for (int t = 0; t < 2; t++)
                acc[t][e] += xv[t].x * wv.x + xv[t].y * wv.y +
                             xv[t].z * wv.z + xv[t].w * wv.w;
        }
    }

    // butterfly reduce: every lane ends with all 16 sums
#pragma unroll
    for (int off = 16; off > 0; off >>= 1)
#pragma unroll
        for (int t = 0; t < 2; t++)
#pragma unroll
            for (int e = 0; e < N_EXP; e++)
                acc[t][e] += __shfl_xor_sync(0xFFFFFFFFu, acc[t][e], off);

    if (lane < 2) {
        const int t = lane;
        const int token = tok0 + t;
        if (token < N) {
            float a[N_EXP];
#pragma unroll
            for (int e = 0; e < N_EXP; e++) a[e] = acc[t][e];

            int e0 = 0; float b0 = a[0];
#pragma unroll
            for (int e = 1; e < N_EXP; e++)
                if (a[e] > b0) { b0 = a[e]; e0 = e; }
            int e1 = (e0 == 0) ? 1 : 0; float b1 = a[e1];
#pragma unroll
            for (int e = 0; e < N_EXP; e++)
                if (e != e0 && a[e] > b1) { b1 = a[e]; e1 = e; }

            float sum = 0.0f;
#pragma unroll
            for (int e = 0; e < N_EXP; e++) sum += expf(a[e] - b0);
            float inv = 1.0f / sum;

            g_eidx[token]     = e0;
            g_eidx[N + token] = e1;
            g_pval[token]     = inv;              // expf(0)*inv
            g_pval[N + token] = expf(b1 - b0) * inv;
        }
    }
}

// ---------------------------------------------------------------------------
// Kernel B: ordered per-expert rank (cumsum in k-major, token order) via
// match_any + popc within warp, per-expert cross-warp scan by warps 0..7.
// PURE COMPUTE: writes only compact g_rank / g_total device globals.
// ---------------------------------------------------------------------------
__global__ void __launch_bounds__(1024) rank_kernel(int N)
{
    const int tid  = threadIdx.x;
    const int warp = tid >> 5;
    const int lane = tid & 31;
    const int total = 2 * N;

    __shared__ int warpcnt[N_EXP][32];
    __shared__ int basesh[N_EXP][32];
    __shared__ int running[N_EXP];
    if (tid < N_EXP) running[tid] = 0;

    const int rounds = (total + 1023) >> 10;
    for (int rd = 0; rd < rounds; rd++) {
        const int i = rd * 1024 + tid;
        const int e = (i < total) ? g_eidx[i] : -1;

        if (tid < N_EXP * 32) ((int*)warpcnt)[tid] = 0;
        __syncthreads();

        unsigned m = __match_any_sync(0xFFFFFFFFu, e);
        int lrank  = __popc(m & ((1u << lane) - 1u));
        int leader = __ffs(m) - 1;
        if (e >= 0 && lane == leader)
            warpcnt[e][warp] = __popc(m);
        __syncthreads();

        if (warp < N_EXP) {
            int runv = running[warp];
            int v = warpcnt[warp][lane];
            int s = v;
#pragma unroll
            for (int off = 1; off < 32; off <<= 1) {
                int u = __shfl_up_sync(0xFFFFFFFFu, s, off);
                if (lane >= off) s += u;
            }
            basesh[warp][lane] = runv + s - v;   // exclusive + running
            if (lane == 31) running[warp] = runv + s;
        }
        __syncthreads();

        if (e >= 0)
            g_rank[i] = basesh[e][warp] + lrank;
        __syncthreads();
    }

    if (tid < N_EXP)
        g_total[tid] = running[tid];
}

// ---------------------------------------------------------------------------
// Kernel C: wide-grid scatter. One thread per routed entry: at most 2 stores
// into the (already-zeroed) output. Block 0 also writes used_capacity.
// ---------------------------------------------------------------------------
__global__ void __launch_bounds__(256) scatter_kernel(
    float* __restrict__ out, int N, int C)
{
    const int i = blockIdx.x * blockDim.x + threadIdx.x;
    const int total = 2 * N;
    const size_t rowsC = (size_t)N * N_EXP * (size_t)C;

    if (i < total) {
        int r = g_rank[i];
        if (r < C) {
            int e = g_eidx[i];
            int k = (i >= N) ? 1 : 0;
            int n = i - k * N;
            size_t pos = ((size_t)n * N_EXP + e) * (size_t)C + r;
            out[8 + pos]         = g_pval[i];
            out[8 + rowsC + pos] = 1.0f;
        }
    }

    if (blockIdx.x == 0 && threadIdx.x < N_EXP) {
        int uc = g_total[threadIdx.x];
        if (uc > C) uc = C;
        out[threadIdx.x] = (float)uc;
    }
}

// ---------------------------------------------------------------------------
extern "C" void kernel_launch(void* const* d_in, const int* in_sizes, int n_in,
                              void* d_out, int out_size)
{
    const float* x   = (const float*)d_in[0];
    const float* w_g = (const float*)d_in[1];
    float* out = (float*)d_out;

    const int D = in_sizes[1] / N_EXP;   // 1024
    const int N = in_sizes[0] / D;       // 4096 tokens

    int C = (int)floorf(2.0f * 1.25f * (float)N / (float)N_EXP);
    C += (C & 1);
    if (C < 4) C = 4;

    // 1) zero the full output (bandwidth floor ~45us for 336MB)
    cudaMemsetAsync(d_out, 0, (size_t)out_size * sizeof(float));

    // 2) router: logits + top-2 + softmax probs (2 tokens/warp, 256 blocks)
    int blocks = (N + 15) / 16;
    router_topk_kernel<<<blocks, 256>>>(x, w_g, N);

    // 3) ordered ranks (pure compute, single block)
    rank_kernel<<<1, 1024>>>(N);

    // 4) wide-grid scatter + used_capacity
    int sblocks = (2 * N + 255) / 256;
    scatter_kernel<<<sblocks, 256>>>(out, N, C);
}